// round 1
// baseline (speedup 1.0000x reference)
#include <cuda_runtime.h>
#include <cuda_bf16.h>
#include <cstdint>

#define T_PTS 524288
#define B_GR  1024
#define Q_C   64
#define NC    10
#define GPB   8

// intermediate pooled features: [B, 128] (v0 | v1)
__device__ float g_X[B_GR * 128];

// -------------------------------------------------------------------------
// Kernel A: per (branch, graph) block. Computes weight-MLP w(t), gaussian
// rep(t, q), accumulates sum_t w*rep into g_X[g, branch*64 + q].
// -------------------------------------------------------------------------
__global__ __launch_bounds__(128) void perslay_kernel(
    const float* __restrict__ diag0, const float* __restrict__ diag1,
    const int* __restrict__ batch0, const int* __restrict__ batch1,
    const float* __restrict__ theta,
    const float* __restrict__ Ww0, const float* __restrict__ bw0,
    const float* __restrict__ Ww1, const float* __restrict__ bw1,
    const float* __restrict__ Wwo, const float* __restrict__ bwo)
{
    __shared__ __align__(16) float sW1[64 * 64];
    __shared__ float sW0x[64], sW0y[64], sB0[64];
    __shared__ __align__(16) float sB1[64];
    __shared__ float sWo[64], sGx[64], sGy[64], sGa[64];
    __shared__ float sRed[4][64];

    const int bid    = blockIdx.x;
    const int branch = bid >> 10;
    const int g      = bid & (B_GR - 1);
    const float* pts = branch ? diag1 : diag0;
    const int* batch = branch ? batch1 : batch0;
    const int tid    = threadIdx.x;

    for (int t = tid; t < 64 * 64; t += 128) sW1[t] = Ww1[t];
    if (tid < 64) {
        sW0x[tid] = Ww0[tid];
        sW0y[tid] = Ww0[64 + tid];
        sB0[tid]  = bw0[tid];
        sB1[tid]  = bw1[tid];
        sWo[tid]  = Wwo[tid];
        const float K2 = -72.13475204444817f;   // -50 * log2(e)   (sigma=0.1)
        const float M2 = 144.26950408889634f;   // +100 * log2(e)
        float tx = theta[2 * tid], ty = theta[2 * tid + 1];
        sGa[tid] = K2 * (tx * tx + ty * ty);
        sGx[tid] = M2 * tx;
        sGy[tid] = M2 * ty;
    }
    const float bwo0 = bwo[0];
    __syncthreads();

    // segment bounds of graph g in sorted batch array
    int lo = 0, hi = T_PTS;
    while (lo < hi) { int m = (lo + hi) >> 1; if (batch[m] < g) lo = m + 1; else hi = m; }
    const int start = lo;
    hi = T_PTS;
    while (lo < hi) { int m = (lo + hi) >> 1; if (batch[m] < g + 1) lo = m + 1; else hi = m; }
    const int end = lo;

    float acc[64];
#pragma unroll
    for (int q = 0; q < 64; q++) acc[q] = 0.f;

    const float2* p2 = reinterpret_cast<const float2*>(pts);

    for (int idx = start + tid; idx < end; idx += 128) {
        const float2 p = p2[idx];

        // ---- layer 1: h = relu(p @ Ww0 + bw0) ----
        float h[64];
#pragma unroll
        for (int k = 0; k < 64; k++)
            h[k] = fmaxf(fmaf(p.x, sW0x[k], fmaf(p.y, sW0y[k], sB0[k])), 0.f);

        // ---- layer 2 + output dot, packed f32x2 over output-neuron pairs ----
        float s = bwo0;
#pragma unroll 1
        for (int jt = 0; jt < 64; jt += 16) {
            unsigned long long a2[8];
#pragma unroll
            for (int u = 0; u < 8; u++)
                a2[u] = *reinterpret_cast<const unsigned long long*>(&sB1[jt + 2 * u]);
#pragma unroll
            for (int i = 0; i < 64; i++) {
                unsigned long long hp;
                asm("mov.b64 %0, {%1, %1};" : "=l"(hp) : "r"(__float_as_uint(h[i])));
                const float* wrow = &sW1[i * 64 + jt];
#pragma unroll
                for (int u = 0; u < 8; u += 2) {
                    const ulonglong2 wv =
                        *reinterpret_cast<const ulonglong2*>(&wrow[2 * u]);
                    asm("fma.rn.f32x2 %0, %1, %2, %0;" : "+l"(a2[u])     : "l"(hp), "l"(wv.x));
                    asm("fma.rn.f32x2 %0, %1, %2, %0;" : "+l"(a2[u + 1]) : "l"(hp), "l"(wv.y));
                }
            }
#pragma unroll
            for (int u = 0; u < 8; u++) {
                unsigned int vlo, vhi;
                asm("mov.b64 {%0, %1}, %2;" : "=r"(vlo), "=r"(vhi) : "l"(a2[u]));
                s = fmaf(fmaxf(__uint_as_float(vlo), 0.f), sWo[jt + 2 * u], s);
                s = fmaf(fmaxf(__uint_as_float(vhi), 0.f), sWo[jt + 2 * u + 1], s);
            }
        }

        // ---- sigmoid ----
        float e;
        asm("ex2.approx.f32 %0, %1;" : "=f"(e) : "f"(-1.4426950408889634f * s));
        float rcp;
        asm("rcp.approx.f32 %0, %1;" : "=f"(rcp) : "f"(1.f + e));
        const float w = rcp;

        // ---- gaussian rep + accumulate ----
        const float kxs = -72.13475204444817f * fmaf(p.x, p.x, p.y * p.y);
#pragma unroll
        for (int q = 0; q < 64; q++) {
            float arg = fmaf(p.x, sGx[q], fmaf(p.y, sGy[q], kxs + sGa[q]));
            float r;
            asm("ex2.approx.f32 %0, %1;" : "=f"(r) : "f"(arg));
            acc[q] = fmaf(w, r, acc[q]);
        }
    }

    // ---- block reduction over q, no atomics ----
    const int lane = tid & 31, wrp = tid >> 5;
#pragma unroll
    for (int q = 0; q < 64; q++) {
        float v = acc[q];
        v += __shfl_xor_sync(0xffffffffu, v, 16);
        v += __shfl_xor_sync(0xffffffffu, v, 8);
        v += __shfl_xor_sync(0xffffffffu, v, 4);
        v += __shfl_xor_sync(0xffffffffu, v, 2);
        v += __shfl_xor_sync(0xffffffffu, v, 1);
        if (lane == 0) sRed[wrp][q] = v;
    }
    __syncthreads();
    if (tid < 64) {
        float r = sRed[0][tid] + sRed[1][tid] + sRed[2][tid] + sRed[3][tid];
        g_X[g * 128 + branch * 64 + tid] = r;
    }
}

// -------------------------------------------------------------------------
// Kernel B: final MLP  [B,144] -> relu 128 -> relu 128 -> 10
// 8 graphs per block; weight rows broadcast-loaded once per block (L1/L2 hot).
// -------------------------------------------------------------------------
__global__ __launch_bounds__(128) void final_mlp_kernel(
    const float* __restrict__ gf,
    const float* __restrict__ Wr0, const float* __restrict__ br0,
    const float* __restrict__ Wr1, const float* __restrict__ br1,
    const float* __restrict__ Wro, const float* __restrict__ bro,
    float* __restrict__ out)
{
    __shared__ float sx[GPB][144];
    __shared__ float sh[GPB][128];
    const int g0  = blockIdx.x * GPB;
    const int tid = threadIdx.x;

    for (int idx = tid; idx < GPB * 144; idx += 128) {
        int gg = idx / 144, c = idx - gg * 144;
        sx[gg][c] = (c < 128) ? g_X[(g0 + gg) * 128 + c]
                              : gf[(g0 + gg) * 16 + (c - 128)];
    }
    __syncthreads();

    // layer 0: 144 -> 128
    {
        float a[GPB];
#pragma unroll
        for (int gg = 0; gg < GPB; gg++) a[gg] = br0[tid];
        for (int i = 0; i < 144; i++) {
            const float wv = Wr0[i * 128 + tid];
#pragma unroll
            for (int gg = 0; gg < GPB; gg++) a[gg] = fmaf(sx[gg][i], wv, a[gg]);
        }
#pragma unroll
        for (int gg = 0; gg < GPB; gg++) sh[gg][tid] = fmaxf(a[gg], 0.f);
    }
    __syncthreads();

    // layer 1: 128 -> 128 (write back into sx)
    {
        float a[GPB];
#pragma unroll
        for (int gg = 0; gg < GPB; gg++) a[gg] = br1[tid];
        for (int i = 0; i < 128; i++) {
            const float wv = Wr1[i * 128 + tid];
#pragma unroll
            for (int gg = 0; gg < GPB; gg++) a[gg] = fmaf(sh[gg][i], wv, a[gg]);
        }
#pragma unroll
        for (int gg = 0; gg < GPB; gg++) sx[gg][tid] = fmaxf(a[gg], 0.f);
    }
    __syncthreads();

    // output layer: 128 -> 10
    if (tid < GPB * NC) {
        const int gg = tid / NC, c = tid - gg * NC;
        float a = bro[c];
        for (int k = 0; k < 128; k++) a = fmaf(sx[gg][k], Wro[k * NC + c], a);
        out[(g0 + gg) * NC + c] = a;
    }
}

// -------------------------------------------------------------------------
extern "C" void kernel_launch(void* const* d_in, const int* in_sizes, int n_in,
                              void* d_out, int out_size)
{
    const float* diag0 = (const float*)d_in[0];
    const float* diag1 = (const float*)d_in[1];
    const float* gf    = (const float*)d_in[2];
    const float* theta = (const float*)d_in[3];
    const float* Ww0   = (const float*)d_in[4];
    const float* bw0   = (const float*)d_in[5];
    const float* Ww1   = (const float*)d_in[6];
    const float* bw1   = (const float*)d_in[7];
    const float* Wwo   = (const float*)d_in[8];
    const float* bwo   = (const float*)d_in[9];
    const float* Wr0   = (const float*)d_in[10];
    const float* br0   = (const float*)d_in[11];
    const float* Wr1   = (const float*)d_in[12];
    const float* br1   = (const float*)d_in[13];
    const float* Wro   = (const float*)d_in[14];
    const float* bro   = (const float*)d_in[15];
    const int*   batch0 = (const int*)d_in[16];
    const int*   batch1 = (const int*)d_in[17];

    perslay_kernel<<<2 * B_GR, 128>>>(diag0, diag1, batch0, batch1, theta,
                                      Ww0, bw0, Ww1, bw1, Wwo, bwo);
    final_mlp_kernel<<<B_GR / GPB, 128>>>(gf, Wr0, br0, Wr1, br1, Wro, bro,
                                          (float*)d_out);
}

// round 2
// speedup vs baseline: 1.4301x; 1.4301x over previous
#include <cuda_runtime.h>
#include <cuda_bf16.h>
#include <cstdint>

#define T_PTS 524288
#define B_GR  1024
#define NC    10

// staging buffers
__device__ float g_w[2 * T_PTS];       // per-point sigmoid weights, both branches
__device__ float g_X[B_GR * 128];      // pooled features (v0 | v1)

// -------------------------------------------------------------------------
// Kernel W: pointwise weight MLP  w(p) = sigmoid(Wo·relu(W1·relu(W0·p+b0)+b1)+bo)
// Graph-independent. f32x2 packed over hidden-unit pairs (i), W1 transposed
// in smem so each LDS.128 feeds exactly 2 FFMA2 with zero repack movs.
// -------------------------------------------------------------------------
__global__ __launch_bounds__(128) void weight_mlp_kernel(
    const float* __restrict__ diag0, const float* __restrict__ diag1,
    const float* __restrict__ Ww0, const float* __restrict__ bw0,
    const float* __restrict__ Ww1, const float* __restrict__ bw1,
    const float* __restrict__ Wwo, const float* __restrict__ bwo)
{
    __shared__ __align__(16) float sW1t[64 * 64];   // [j][i] : W1 transposed
    __shared__ float sW0x[64], sW0y[64], sB0[64], sB1[64], sWo[64];

    const int tid = threadIdx.x;
    for (int t = tid; t < 64 * 64; t += 128) {
        int i = t >> 6, j = t & 63;
        sW1t[j * 64 + i] = Ww1[t];          // Ww1[i*64 + j] -> sW1t[j][i]
    }
    if (tid < 64) {
        sW0x[tid] = Ww0[tid];
        sW0y[tid] = Ww0[64 + tid];
        sB0[tid]  = bw0[tid];
        sB1[tid]  = bw1[tid];
        sWo[tid]  = Wwo[tid];
    }
    const float bwo0 = bwo[0];
    __syncthreads();

    const int branch = blockIdx.x >> 10;
    const float2* p2 = reinterpret_cast<const float2*>(branch ? diag1 : diag0);
    float* wout      = g_w + branch * T_PTS;
    const int base   = (blockIdx.x & 1023) * 512;

#pragma unroll 1
    for (int it = 0; it < 4; it++) {
        const int idx  = base + it * 128 + tid;
        const float2 p = p2[idx];

        // ---- layer 1: h = relu(W0·p + b0), packed into 32 f32x2 regs ----
        unsigned long long h2[32];
#pragma unroll
        for (int k = 0; k < 32; k++) {
            float a = fmaxf(fmaf(p.x, sW0x[2 * k],     fmaf(p.y, sW0y[2 * k],     sB0[2 * k])),     0.f);
            float b = fmaxf(fmaf(p.x, sW0x[2 * k + 1], fmaf(p.y, sW0y[2 * k + 1], sB0[2 * k + 1])), 0.f);
            asm("mov.b64 %0, {%1, %2};" : "=l"(h2[k])
                : "r"(__float_as_uint(a)), "r"(__float_as_uint(b)));
        }

        // ---- layer 2 + output dot: col tiles of 16, i-pair-packed FFMA2 ----
        float s = bwo0;
#pragma unroll 1
        for (int jt = 0; jt < 64; jt += 16) {
            unsigned long long a2[16];
#pragma unroll
            for (int j = 0; j < 16; j++)
                a2[j] = (unsigned long long)__float_as_uint(sB1[jt + j]); // {bias, 0}

#pragma unroll 4
            for (int ip2 = 0; ip2 < 16; ip2++) {
                const unsigned long long hp0 = h2[2 * ip2];
                const unsigned long long hp1 = h2[2 * ip2 + 1];
                const float* wbase = &sW1t[jt * 64 + 4 * ip2];
#pragma unroll
                for (int j = 0; j < 16; j++) {
                    const ulonglong2 wv =
                        *reinterpret_cast<const ulonglong2*>(wbase + j * 64);
                    asm("fma.rn.f32x2 %0, %1, %2, %0;" : "+l"(a2[j]) : "l"(hp0), "l"(wv.x));
                    asm("fma.rn.f32x2 %0, %1, %2, %0;" : "+l"(a2[j]) : "l"(hp1), "l"(wv.y));
                }
            }
#pragma unroll
            for (int j = 0; j < 16; j++) {
                unsigned lo, hi;
                asm("mov.b64 {%0, %1}, %2;" : "=r"(lo), "=r"(hi) : "l"(a2[j]));
                float v = __uint_as_float(lo) + __uint_as_float(hi);
                s = fmaf(fmaxf(v, 0.f), sWo[jt + j], s);
            }
        }

        // ---- sigmoid ----
        float e, r;
        asm("ex2.approx.f32 %0, %1;" : "=f"(e) : "f"(-1.4426950408889634f * s));
        asm("rcp.approx.f32 %0, %1;" : "=f"(r) : "f"(1.f + e));
        wout[idx] = r;
    }
}

// -------------------------------------------------------------------------
// Kernel G: gaussian rep + weighted segment-sum pooling.
// One block per (branch, graph); acc[64] per thread; MUFU(EX2)-bound.
// -------------------------------------------------------------------------
__global__ __launch_bounds__(128) void gauss_pool_kernel(
    const float* __restrict__ diag0, const float* __restrict__ diag1,
    const int* __restrict__ batch0, const int* __restrict__ batch1,
    const float* __restrict__ theta)
{
    __shared__ float sGx[64], sGy[64], sGa[64];
    __shared__ float sRed[4][64];

    const int bid    = blockIdx.x;
    const int branch = bid >> 10;
    const int g      = bid & (B_GR - 1);
    const int tid    = threadIdx.x;
    const float2* p2   = reinterpret_cast<const float2*>(branch ? diag1 : diag0);
    const int* batch   = branch ? batch1 : batch0;
    const float* wbuf  = g_w + branch * T_PTS;

    if (tid < 64) {
        const float K2 = -72.13475204444817f;   // -50 * log2(e)   (sigma=0.1)
        const float M2 = 144.26950408889634f;   // +100 * log2(e)
        float tx = theta[2 * tid], ty = theta[2 * tid + 1];
        sGa[tid] = K2 * (tx * tx + ty * ty);
        sGx[tid] = M2 * tx;
        sGy[tid] = M2 * ty;
    }
    __syncthreads();

    int lo = 0, hi = T_PTS;
    while (lo < hi) { int m = (lo + hi) >> 1; if (batch[m] < g) lo = m + 1; else hi = m; }
    const int start = lo;
    hi = T_PTS;
    while (lo < hi) { int m = (lo + hi) >> 1; if (batch[m] < g + 1) lo = m + 1; else hi = m; }
    const int end = lo;

    float acc[64];
#pragma unroll
    for (int q = 0; q < 64; q++) acc[q] = 0.f;

    for (int idx = start + tid; idx < end; idx += 128) {
        const float2 p = p2[idx];
        const float  w = wbuf[idx];
        const float kxs = -72.13475204444817f * fmaf(p.x, p.x, p.y * p.y);
#pragma unroll
        for (int q = 0; q < 64; q++) {
            float arg = fmaf(p.x, sGx[q], fmaf(p.y, sGy[q], sGa[q])) + kxs;
            float r;
            asm("ex2.approx.f32 %0, %1;" : "=f"(r) : "f"(arg));
            acc[q] = fmaf(w, r, acc[q]);
        }
    }

    const int lane = tid & 31, wrp = tid >> 5;
#pragma unroll
    for (int q = 0; q < 64; q++) {
        float v = acc[q];
        v += __shfl_xor_sync(0xffffffffu, v, 16);
        v += __shfl_xor_sync(0xffffffffu, v, 8);
        v += __shfl_xor_sync(0xffffffffu, v, 4);
        v += __shfl_xor_sync(0xffffffffu, v, 2);
        v += __shfl_xor_sync(0xffffffffu, v, 1);
        if (lane == 0) sRed[wrp][q] = v;
    }
    __syncthreads();
    if (tid < 64)
        g_X[g * 128 + branch * 64 + tid]
            = sRed[0][tid] + sRed[1][tid] + sRed[2][tid] + sRed[3][tid];
}

// -------------------------------------------------------------------------
// Kernel B: final MLP [B,144] -> relu 128 -> relu 128 -> 10.
// 2 graphs/block, 512 blocks -> weights L1-resident, high occupancy.
// -------------------------------------------------------------------------
#define GPB 2
__global__ __launch_bounds__(128) void final_mlp_kernel(
    const float* __restrict__ gf,
    const float* __restrict__ Wr0, const float* __restrict__ br0,
    const float* __restrict__ Wr1, const float* __restrict__ br1,
    const float* __restrict__ Wro, const float* __restrict__ bro,
    float* __restrict__ out)
{
    __shared__ float sx[GPB][144];
    __shared__ float sh[GPB][128];
    const int g0  = blockIdx.x * GPB;
    const int tid = threadIdx.x;

    for (int idx = tid; idx < GPB * 144; idx += 128) {
        int gg = idx / 144, c = idx - gg * 144;
        sx[gg][c] = (c < 128) ? g_X[(g0 + gg) * 128 + c]
                              : gf[(g0 + gg) * 16 + (c - 128)];
    }
    __syncthreads();

    {
        float a0 = br0[tid], a1 = a0;
#pragma unroll 8
        for (int i = 0; i < 144; i++) {
            const float wv = Wr0[i * 128 + tid];
            a0 = fmaf(sx[0][i], wv, a0);
            a1 = fmaf(sx[1][i], wv, a1);
        }
        sh[0][tid] = fmaxf(a0, 0.f);
        sh[1][tid] = fmaxf(a1, 0.f);
    }
    __syncthreads();

    {
        float a0 = br1[tid], a1 = a0;
#pragma unroll 8
        for (int i = 0; i < 128; i++) {
            const float wv = Wr1[i * 128 + tid];
            a0 = fmaf(sh[0][i], wv, a0);
            a1 = fmaf(sh[1][i], wv, a1);
        }
        sx[0][tid] = fmaxf(a0, 0.f);
        sx[1][tid] = fmaxf(a1, 0.f);
    }
    __syncthreads();

    if (tid < GPB * NC) {
        const int gg = tid / NC, c = tid - gg * NC;
        float a = bro[c];
#pragma unroll 8
        for (int k = 0; k < 128; k++) a = fmaf(sx[gg][k], Wro[k * NC + c], a);
        out[(g0 + gg) * NC + c] = a;
    }
}

// -------------------------------------------------------------------------
extern "C" void kernel_launch(void* const* d_in, const int* in_sizes, int n_in,
                              void* d_out, int out_size)
{
    const float* diag0 = (const float*)d_in[0];
    const float* diag1 = (const float*)d_in[1];
    const float* gf    = (const float*)d_in[2];
    const float* theta = (const float*)d_in[3];
    const float* Ww0   = (const float*)d_in[4];
    const float* bw0   = (const float*)d_in[5];
    const float* Ww1   = (const float*)d_in[6];
    const float* bw1   = (const float*)d_in[7];
    const float* Wwo   = (const float*)d_in[8];
    const float* bwo   = (const float*)d_in[9];
    const float* Wr0   = (const float*)d_in[10];
    const float* br0   = (const float*)d_in[11];
    const float* Wr1   = (const float*)d_in[12];
    const float* br1   = (const float*)d_in[13];
    const float* Wro   = (const float*)d_in[14];
    const float* bro   = (const float*)d_in[15];
    const int*   batch0 = (const int*)d_in[16];
    const int*   batch1 = (const int*)d_in[17];

    weight_mlp_kernel<<<2 * B_GR, 128>>>(diag0, diag1,
                                         Ww0, bw0, Ww1, bw1, Wwo, bwo);
    gauss_pool_kernel<<<2 * B_GR, 128>>>(diag0, diag1, batch0, batch1, theta);
    final_mlp_kernel<<<B_GR / GPB, 128>>>(gf, Wr0, br0, Wr1, br1, Wro, bro,
                                          (float*)d_out);
}

// round 3
// speedup vs baseline: 2.3041x; 1.6112x over previous
#include <cuda_runtime.h>
#include <cuda_bf16.h>
#include <cstdint>

#define T_PTS 524288
#define B_GR  1024
#define NC    10

typedef unsigned long long u64;

// staging buffers
__device__ float g_w[2 * T_PTS];       // per-point sigmoid weights
__device__ float g_X[B_GR * 128];      // pooled features (v0 | v1)

// -------------------------------------------------------------------------
// Kernel W: pointwise weight MLP as a register-tiled GEMM.
// Warp tile = 32 points x 64 outputs; thread = 8 pts x 8 outs (f32x2-packed
// over point pairs). H staged in smem transposed so point-pairs are native
// f32x2 loads. LDS per point: 8x LDS.128 (was 32).
// -------------------------------------------------------------------------
__global__ __launch_bounds__(128) void weight_mlp_kernel(
    const float* __restrict__ diag0, const float* __restrict__ diag1,
    const float* __restrict__ Ww0, const float* __restrict__ bw0,
    const float* __restrict__ Ww1, const float* __restrict__ bw1,
    const float* __restrict__ Wwo, const float* __restrict__ bwo)
{
    __shared__ __align__(16) float sW1[64 * 64];   // [k][o], no transpose needed
    __shared__ __align__(16) float4 sC0[64];       // {W0x, W0y, b0, -}
    __shared__ float sB1[64], sWo[64];
    extern __shared__ __align__(16) float sH[];    // [4 warps][64 k][32 pts]

    const int tid = threadIdx.x;
    for (int t = tid; t < 4096; t += 128) sW1[t] = Ww1[t];
    if (tid < 64) {
        sC0[tid] = make_float4(Ww0[tid], Ww0[64 + tid], bw0[tid], 0.f);
        sB1[tid] = bw1[tid];
        sWo[tid] = Wwo[tid];
    }
    const float bwo0 = bwo[0];
    __syncthreads();

    const int branch = blockIdx.x >> 10;
    const float2* p2 = (const float2*)(branch ? diag1 : diag0);
    float* wout      = g_w + branch * T_PTS;

    const int wrp = tid >> 5, lane = tid & 31;
    const int pg = lane & 3, og = lane >> 2;
    const int blkbase = (blockIdx.x & 1023) * 512 + wrp * 128;
    float* myH = sH + wrp * (64 * 32);

#pragma unroll 1
    for (int t = 0; t < 4; t++) {
        const int tbase = blkbase + t * 32;

        // ---- layer 1: h[k] for this lane's point -> smem transposed ----
        const float2 p = p2[tbase + lane];
#pragma unroll 8
        for (int k = 0; k < 64; k++) {
            const float4 c = sC0[k];
            myH[k * 32 + lane] = fmaxf(fmaf(p.x, c.x, fmaf(p.y, c.y, c.z)), 0.f);
        }
        __syncwarp();

        // ---- GEMM: acc[4 pt-pairs][8 outs], f32x2 packed over points ----
        u64 acc[4][8];
#pragma unroll
        for (int o = 0; o < 8; o++) {
            u64 bdup;
            asm("mov.b64 %0, {%1,%1};" : "=l"(bdup)
                : "r"(__float_as_uint(sB1[og * 8 + o])));
#pragma unroll
            for (int pp = 0; pp < 4; pp++) acc[pp][o] = bdup;
        }

#pragma unroll 2
        for (int k = 0; k < 64; k++) {
            const ulonglong2 hA = *(const ulonglong2*)&myH[k * 32 + pg * 8];
            const ulonglong2 hB = *(const ulonglong2*)&myH[k * 32 + pg * 8 + 4];
            const u64 hp[4] = {hA.x, hA.y, hB.x, hB.y};
            const float4 w0 = *(const float4*)&sW1[k * 64 + og * 8];
            const float4 w1 = *(const float4*)&sW1[k * 64 + og * 8 + 4];
            const float wf[8] = {w0.x, w0.y, w0.z, w0.w, w1.x, w1.y, w1.z, w1.w};
#pragma unroll
            for (int o = 0; o < 8; o++) {
                u64 wd;
                asm("mov.b64 %0, {%1,%1};" : "=l"(wd)
                    : "r"(__float_as_uint(wf[o])));
#pragma unroll
                for (int pp = 0; pp < 4; pp++)
                    asm("fma.rn.f32x2 %0, %1, %2, %0;"
                        : "+l"(acc[pp][o]) : "l"(hp[pp]), "l"(wd));
            }
        }

        // ---- epilogue: s_p = sum_o relu(z)*Wo, reduce over out-groups ----
        float s[8];
#pragma unroll
        for (int i = 0; i < 8; i++) s[i] = 0.f;
#pragma unroll
        for (int o = 0; o < 8; o++) {
            const float wo = sWo[og * 8 + o];
#pragma unroll
            for (int pp = 0; pp < 4; pp++) {
                unsigned lo, hi;
                asm("mov.b64 {%0,%1}, %2;" : "=r"(lo), "=r"(hi) : "l"(acc[pp][o]));
                s[2 * pp]     = fmaf(fmaxf(__uint_as_float(lo), 0.f), wo, s[2 * pp]);
                s[2 * pp + 1] = fmaf(fmaxf(__uint_as_float(hi), 0.f), wo, s[2 * pp + 1]);
            }
        }
#pragma unroll
        for (int i = 0; i < 8; i++) {
            s[i] += __shfl_xor_sync(0xffffffffu, s[i], 4);
            s[i] += __shfl_xor_sync(0xffffffffu, s[i], 8);
            s[i] += __shfl_xor_sync(0xffffffffu, s[i], 16);
        }
        if (lane < 4) {   // pg = lane, og = 0: full sums for pts tbase+lane*8+i
            float r[8];
#pragma unroll
            for (int i = 0; i < 8; i++) {
                float e, rc;
                asm("ex2.approx.f32 %0, %1;" : "=f"(e)
                    : "f"(-1.4426950408889634f * (s[i] + bwo0)));
                asm("rcp.approx.f32 %0, %1;" : "=f"(rc) : "f"(1.f + e));
                r[i] = rc;
            }
            float4* dst = (float4*)&wout[tbase + lane * 8];
            dst[0] = make_float4(r[0], r[1], r[2], r[3]);
            dst[1] = make_float4(r[4], r[5], r[6], r[7]);
        }
        __syncwarp();
    }
}

// -------------------------------------------------------------------------
// Kernel G: gaussian rep + weighted segment-sum pooling (unchanged).
// -------------------------------------------------------------------------
__global__ __launch_bounds__(128) void gauss_pool_kernel(
    const float* __restrict__ diag0, const float* __restrict__ diag1,
    const int* __restrict__ batch0, const int* __restrict__ batch1,
    const float* __restrict__ theta)
{
    __shared__ float sGx[64], sGy[64], sGa[64];
    __shared__ float sRed[4][64];

    const int bid    = blockIdx.x;
    const int branch = bid >> 10;
    const int g      = bid & (B_GR - 1);
    const int tid    = threadIdx.x;
    const float2* p2  = (const float2*)(branch ? diag1 : diag0);
    const int* batch  = branch ? batch1 : batch0;
    const float* wbuf = g_w + branch * T_PTS;

    if (tid < 64) {
        const float K2 = -72.13475204444817f;   // -50 * log2(e)
        const float M2 = 144.26950408889634f;   // +100 * log2(e)
        float tx = theta[2 * tid], ty = theta[2 * tid + 1];
        sGa[tid] = K2 * (tx * tx + ty * ty);
        sGx[tid] = M2 * tx;
        sGy[tid] = M2 * ty;
    }
    __syncthreads();

    int lo = 0, hi = T_PTS;
    while (lo < hi) { int m = (lo + hi) >> 1; if (batch[m] < g) lo = m + 1; else hi = m; }
    const int start = lo;
    hi = T_PTS;
    while (lo < hi) { int m = (lo + hi) >> 1; if (batch[m] < g + 1) lo = m + 1; else hi = m; }
    const int end = lo;

    float acc[64];
#pragma unroll
    for (int q = 0; q < 64; q++) acc[q] = 0.f;

    for (int idx = start + tid; idx < end; idx += 128) {
        const float2 p = p2[idx];
        const float  w = wbuf[idx];
        const float kxs = -72.13475204444817f * fmaf(p.x, p.x, p.y * p.y);
#pragma unroll
        for (int q = 0; q < 64; q++) {
            float arg = fmaf(p.x, sGx[q], fmaf(p.y, sGy[q], sGa[q])) + kxs;
            float r;
            asm("ex2.approx.f32 %0, %1;" : "=f"(r) : "f"(arg));
            acc[q] = fmaf(w, r, acc[q]);
        }
    }

    const int lane = tid & 31, wrp = tid >> 5;
#pragma unroll
    for (int q = 0; q < 64; q++) {
        float v = acc[q];
        v += __shfl_xor_sync(0xffffffffu, v, 16);
        v += __shfl_xor_sync(0xffffffffu, v, 8);
        v += __shfl_xor_sync(0xffffffffu, v, 4);
        v += __shfl_xor_sync(0xffffffffu, v, 2);
        v += __shfl_xor_sync(0xffffffffu, v, 1);
        if (lane == 0) sRed[wrp][q] = v;
    }
    __syncthreads();
    if (tid < 64)
        g_X[g * 128 + branch * 64 + tid]
            = sRed[0][tid] + sRed[1][tid] + sRed[2][tid] + sRed[3][tid];
}

// -------------------------------------------------------------------------
// Kernel B: final MLP [B,144] -> relu 128 -> relu 128 -> 10 (unchanged).
// -------------------------------------------------------------------------
#define GPB 2
__global__ __launch_bounds__(128) void final_mlp_kernel(
    const float* __restrict__ gf,
    const float* __restrict__ Wr0, const float* __restrict__ br0,
    const float* __restrict__ Wr1, const float* __restrict__ br1,
    const float* __restrict__ Wro, const float* __restrict__ bro,
    float* __restrict__ out)
{
    __shared__ float sx[GPB][144];
    __shared__ float sh[GPB][128];
    const int g0  = blockIdx.x * GPB;
    const int tid = threadIdx.x;

    for (int idx = tid; idx < GPB * 144; idx += 128) {
        int gg = idx / 144, c = idx - gg * 144;
        sx[gg][c] = (c < 128) ? g_X[(g0 + gg) * 128 + c]
                              : gf[(g0 + gg) * 16 + (c - 128)];
    }
    __syncthreads();

    {
        float a0 = br0[tid], a1 = a0;
#pragma unroll 8
        for (int i = 0; i < 144; i++) {
            const float wv = Wr0[i * 128 + tid];
            a0 = fmaf(sx[0][i], wv, a0);
            a1 = fmaf(sx[1][i], wv, a1);
        }
        sh[0][tid] = fmaxf(a0, 0.f);
        sh[1][tid] = fmaxf(a1, 0.f);
    }
    __syncthreads();

    {
        float a0 = br1[tid], a1 = a0;
#pragma unroll 8
        for (int i = 0; i < 128; i++) {
            const float wv = Wr1[i * 128 + tid];
            a0 = fmaf(sh[0][i], wv, a0);
            a1 = fmaf(sh[1][i], wv, a1);
        }
        sx[0][tid] = fmaxf(a0, 0.f);
        sx[1][tid] = fmaxf(a1, 0.f);
    }
    __syncthreads();

    if (tid < GPB * NC) {
        const int gg = tid / NC, c = tid - gg * NC;
        float a = bro[c];
#pragma unroll 8
        for (int k = 0; k < 128; k++) a = fmaf(sx[gg][k], Wro[k * NC + c], a);
        out[(g0 + gg) * NC + c] = a;
    }
}

// -------------------------------------------------------------------------
extern "C" void kernel_launch(void* const* d_in, const int* in_sizes, int n_in,
                              void* d_out, int out_size)
{
    const float* diag0 = (const float*)d_in[0];
    const float* diag1 = (const float*)d_in[1];
    const float* gf    = (const float*)d_in[2];
    const float* theta = (const float*)d_in[3];
    const float* Ww0   = (const float*)d_in[4];
    const float* bw0   = (const float*)d_in[5];
    const float* Ww1   = (const float*)d_in[6];
    const float* bw1   = (const float*)d_in[7];
    const float* Wwo   = (const float*)d_in[8];
    const float* bwo   = (const float*)d_in[9];
    const float* Wr0   = (const float*)d_in[10];
    const float* br0   = (const float*)d_in[11];
    const float* Wr1   = (const float*)d_in[12];
    const float* br1   = (const float*)d_in[13];
    const float* Wro   = (const float*)d_in[14];
    const float* bro   = (const float*)d_in[15];
    const int*   batch0 = (const int*)d_in[16];
    const int*   batch1 = (const int*)d_in[17];

    const int dynsmem = 4 * 64 * 32 * (int)sizeof(float);   // 32 KB H staging
    static int smem_set = 0;
    if (!smem_set) {
        cudaFuncSetAttribute(weight_mlp_kernel,
                             cudaFuncAttributeMaxDynamicSharedMemorySize, dynsmem);
        smem_set = 1;
    }

    weight_mlp_kernel<<<2 * B_GR, 128, dynsmem>>>(diag0, diag1,
                                                  Ww0, bw0, Ww1, bw1, Wwo, bwo);
    gauss_pool_kernel<<<2 * B_GR, 128>>>(diag0, diag1, batch0, batch1, theta);
    final_mlp_kernel<<<B_GR / GPB, 128>>>(gf, Wr0, br0, Wr1, br1, Wro, bro,
                                          (float*)d_out);
}

// round 4
// speedup vs baseline: 3.0823x; 1.3377x over previous
#include <cuda_runtime.h>
#include <cuda_bf16.h>
#include <cstdint>

#define T_PTS 524288
#define B_GR  1024
#define NC    10

typedef unsigned long long u64;

// staging buffers
__device__ float g_w[2 * T_PTS];       // per-point sigmoid weights
__device__ float g_X[B_GR * 128];      // pooled features (v0 | v1)

// -------------------------------------------------------------------------
// Kernel W: pointwise weight MLP as a register-tiled GEMM.
// Warp tile = 32 pts x 64 outs; thread = 8 pts x 8 outs (f32x2 over pt pairs).
// k-loop split in two halves of 32 so the H staging buffer is 16KB (not 32KB)
// -> 5 resident blocks/SM instead of 4.
// -------------------------------------------------------------------------
__global__ __launch_bounds__(128) void weight_mlp_kernel(
    const float* __restrict__ diag0, const float* __restrict__ diag1,
    const float* __restrict__ Ww0, const float* __restrict__ bw0,
    const float* __restrict__ Ww1, const float* __restrict__ bw1,
    const float* __restrict__ Wwo, const float* __restrict__ bwo)
{
    __shared__ __align__(16) float sW1[64 * 64];   // [k][o]
    __shared__ __align__(16) float4 sC0[64];       // {W0x, W0y, b0, -}
    __shared__ float sB1[64], sWo[64];
    extern __shared__ __align__(16) float sH[];    // [4 warps][32 k][32 pts]

    const int tid = threadIdx.x;
    for (int t = tid; t < 4096; t += 128) sW1[t] = Ww1[t];
    if (tid < 64) {
        sC0[tid] = make_float4(Ww0[tid], Ww0[64 + tid], bw0[tid], 0.f);
        sB1[tid] = bw1[tid];
        sWo[tid] = Wwo[tid];
    }
    const float bwo0 = bwo[0];
    __syncthreads();

    const int branch = blockIdx.x >> 10;
    const float2* p2 = (const float2*)(branch ? diag1 : diag0);
    float* wout      = g_w + branch * T_PTS;

    const int wrp = tid >> 5, lane = tid & 31;
    const int pg = lane & 3, og = lane >> 2;
    const int blkbase = (blockIdx.x & 1023) * 512 + wrp * 128;
    float* myH = sH + wrp * (32 * 32);

#pragma unroll 1
    for (int t = 0; t < 4; t++) {
        const int tbase = blkbase + t * 32;
        const float2 p = p2[tbase + lane];

        u64 acc[4][8];
#pragma unroll
        for (int o = 0; o < 8; o++) {
            u64 bdup;
            asm("mov.b64 %0, {%1,%1};" : "=l"(bdup)
                : "r"(__float_as_uint(sB1[og * 8 + o])));
#pragma unroll
            for (int pp = 0; pp < 4; pp++) acc[pp][o] = bdup;
        }

#pragma unroll 1
        for (int half = 0; half < 2; half++) {
            const int k0 = half * 32;

            // ---- layer 1 for this half's k range ----
#pragma unroll 8
            for (int k = 0; k < 32; k++) {
                const float4 c = sC0[k0 + k];
                myH[k * 32 + lane] =
                    fmaxf(fmaf(p.x, c.x, fmaf(p.y, c.y, c.z)), 0.f);
            }
            __syncwarp();

            // ---- GEMM over 32 k ----
#pragma unroll 2
            for (int k = 0; k < 32; k++) {
                const ulonglong2 hA = *(const ulonglong2*)&myH[k * 32 + pg * 8];
                const ulonglong2 hB = *(const ulonglong2*)&myH[k * 32 + pg * 8 + 4];
                const u64 hp[4] = {hA.x, hA.y, hB.x, hB.y};
                const float4 w0 = *(const float4*)&sW1[(k0 + k) * 64 + og * 8];
                const float4 w1 = *(const float4*)&sW1[(k0 + k) * 64 + og * 8 + 4];
                const float wf[8] = {w0.x, w0.y, w0.z, w0.w,
                                     w1.x, w1.y, w1.z, w1.w};
#pragma unroll
                for (int o = 0; o < 8; o++) {
                    u64 wd;
                    asm("mov.b64 %0, {%1,%1};" : "=l"(wd)
                        : "r"(__float_as_uint(wf[o])));
#pragma unroll
                    for (int pp = 0; pp < 4; pp++)
                        asm("fma.rn.f32x2 %0, %1, %2, %0;"
                            : "+l"(acc[pp][o]) : "l"(hp[pp]), "l"(wd));
                }
            }
            __syncwarp();
        }

        // ---- epilogue: s_p = sum_o relu(z)*Wo, reduce over out-groups ----
        float s[8];
#pragma unroll
        for (int i = 0; i < 8; i++) s[i] = 0.f;
#pragma unroll
        for (int o = 0; o < 8; o++) {
            const float wo = sWo[og * 8 + o];
#pragma unroll
            for (int pp = 0; pp < 4; pp++) {
                unsigned lo, hi;
                asm("mov.b64 {%0,%1}, %2;" : "=r"(lo), "=r"(hi) : "l"(acc[pp][o]));
                s[2 * pp]     = fmaf(fmaxf(__uint_as_float(lo), 0.f), wo, s[2 * pp]);
                s[2 * pp + 1] = fmaf(fmaxf(__uint_as_float(hi), 0.f), wo, s[2 * pp + 1]);
            }
        }
#pragma unroll
        for (int i = 0; i < 8; i++) {
            s[i] += __shfl_xor_sync(0xffffffffu, s[i], 4);
            s[i] += __shfl_xor_sync(0xffffffffu, s[i], 8);
            s[i] += __shfl_xor_sync(0xffffffffu, s[i], 16);
        }
        if (lane < 4) {   // pg = lane, og = 0: full sums for pts tbase+lane*8+i
            float r[8];
#pragma unroll
            for (int i = 0; i < 8; i++) {
                float e, rc;
                asm("ex2.approx.f32 %0, %1;" : "=f"(e)
                    : "f"(-1.4426950408889634f * (s[i] + bwo0)));
                asm("rcp.approx.f32 %0, %1;" : "=f"(rc) : "f"(1.f + e));
                r[i] = rc;
            }
            float4* dst = (float4*)&wout[tbase + lane * 8];
            dst[0] = make_float4(r[0], r[1], r[2], r[3]);
            dst[1] = make_float4(r[4], r[5], r[6], r[7]);
        }
        __syncwarp();
    }
}

// -------------------------------------------------------------------------
// Kernel G: gaussian rep + weighted pooling, q-per-lane layout.
// Lane l owns q = l and q = l+32: theta constants live in 6 registers,
// points broadcast across the warp with shuffles. acc = 2 regs, no LDS.
// -------------------------------------------------------------------------
__global__ __launch_bounds__(128) void gauss_pool_kernel(
    const float* __restrict__ diag0, const float* __restrict__ diag1,
    const int* __restrict__ batch0, const int* __restrict__ batch1,
    const float* __restrict__ theta)
{
    __shared__ float sRed[4][64];

    const int bid    = blockIdx.x;
    const int branch = bid >> 10;
    const int g      = bid & (B_GR - 1);
    const int tid    = threadIdx.x;
    const int lane   = tid & 31, wrp = tid >> 5;
    const float2* p2  = (const float2*)(branch ? diag1 : diag0);
    const int* batch  = branch ? batch1 : batch0;
    const float* wbuf = g_w + branch * T_PTS;

    const float K2 = -72.13475204444817f;   // -50 * log2(e)  (sigma=0.1)
    const float M2 = 144.26950408889634f;   // +100 * log2(e)
    const float2 t0 = ((const float2*)theta)[lane];
    const float2 t1 = ((const float2*)theta)[lane + 32];
    const float gx0 = M2 * t0.x, gy0 = M2 * t0.y;
    const float ga0 = K2 * fmaf(t0.x, t0.x, t0.y * t0.y);
    const float gx1 = M2 * t1.x, gy1 = M2 * t1.y;
    const float ga1 = K2 * fmaf(t1.x, t1.x, t1.y * t1.y);

    int lo = 0, hi = T_PTS;
    while (lo < hi) { int m = (lo + hi) >> 1; if (batch[m] < g) lo = m + 1; else hi = m; }
    const int start = lo;
    hi = T_PTS;
    while (lo < hi) { int m = (lo + hi) >> 1; if (batch[m] < g + 1) lo = m + 1; else hi = m; }
    const int end = lo;

    float acc0 = 0.f, acc1 = 0.f;

    for (int base = start + wrp * 32; base < end; base += 128) {
        const int n = min(32, end - base);
        float2 p = make_float2(0.f, 0.f);
        float  w = 0.f;
        if (lane < n) { p = p2[base + lane]; w = wbuf[base + lane]; }
        const float c = K2 * fmaf(p.x, p.x, p.y * p.y);

        if (n == 32) {
#pragma unroll 8
            for (int j = 0; j < 32; j++) {
                const float px = __shfl_sync(0xffffffffu, p.x, j);
                const float py = __shfl_sync(0xffffffffu, p.y, j);
                const float cc = __shfl_sync(0xffffffffu, c,   j);
                const float ww = __shfl_sync(0xffffffffu, w,   j);
                float a0 = fmaf(px, gx0, fmaf(py, gy0, ga0 + cc));
                float a1 = fmaf(px, gx1, fmaf(py, gy1, ga1 + cc));
                float r0, r1;
                asm("ex2.approx.f32 %0, %1;" : "=f"(r0) : "f"(a0));
                asm("ex2.approx.f32 %0, %1;" : "=f"(r1) : "f"(a1));
                acc0 = fmaf(ww, r0, acc0);
                acc1 = fmaf(ww, r1, acc1);
            }
        } else {
            for (int j = 0; j < n; j++) {
                const float px = __shfl_sync(0xffffffffu, p.x, j);
                const float py = __shfl_sync(0xffffffffu, p.y, j);
                const float cc = __shfl_sync(0xffffffffu, c,   j);
                const float ww = __shfl_sync(0xffffffffu, w,   j);
                float a0 = fmaf(px, gx0, fmaf(py, gy0, ga0 + cc));
                float a1 = fmaf(px, gx1, fmaf(py, gy1, ga1 + cc));
                float r0, r1;
                asm("ex2.approx.f32 %0, %1;" : "=f"(r0) : "f"(a0));
                asm("ex2.approx.f32 %0, %1;" : "=f"(r1) : "f"(a1));
                acc0 = fmaf(ww, r0, acc0);
                acc1 = fmaf(ww, r1, acc1);
            }
        }
    }

    sRed[wrp][lane]      = acc0;
    sRed[wrp][lane + 32] = acc1;
    __syncthreads();
    if (tid < 64)
        g_X[g * 128 + branch * 64 + tid]
            = sRed[0][tid] + sRed[1][tid] + sRed[2][tid] + sRed[3][tid];
}

// -------------------------------------------------------------------------
// Kernel B: final MLP [B,144] -> relu 128 -> relu 128 -> 10.
// -------------------------------------------------------------------------
#define GPB 2
__global__ __launch_bounds__(128) void final_mlp_kernel(
    const float* __restrict__ gf,
    const float* __restrict__ Wr0, const float* __restrict__ br0,
    const float* __restrict__ Wr1, const float* __restrict__ br1,
    const float* __restrict__ Wro, const float* __restrict__ bro,
    float* __restrict__ out)
{
    __shared__ float sx[GPB][144];
    __shared__ float sh[GPB][128];
    const int g0  = blockIdx.x * GPB;
    const int tid = threadIdx.x;

    for (int idx = tid; idx < GPB * 144; idx += 128) {
        int gg = idx / 144, c = idx - gg * 144;
        sx[gg][c] = (c < 128) ? g_X[(g0 + gg) * 128 + c]
                              : gf[(g0 + gg) * 16 + (c - 128)];
    }
    __syncthreads();

    {
        float a0 = br0[tid], a1 = a0;
#pragma unroll 8
        for (int i = 0; i < 144; i++) {
            const float wv = Wr0[i * 128 + tid];
            a0 = fmaf(sx[0][i], wv, a0);
            a1 = fmaf(sx[1][i], wv, a1);
        }
        sh[0][tid] = fmaxf(a0, 0.f);
        sh[1][tid] = fmaxf(a1, 0.f);
    }
    __syncthreads();

    {
        float a0 = br1[tid], a1 = a0;
#pragma unroll 8
        for (int i = 0; i < 128; i++) {
            const float wv = Wr1[i * 128 + tid];
            a0 = fmaf(sh[0][i], wv, a0);
            a1 = fmaf(sh[1][i], wv, a1);
        }
        sx[0][tid] = fmaxf(a0, 0.f);
        sx[1][tid] = fmaxf(a1, 0.f);
    }
    __syncthreads();

    if (tid < GPB * NC) {
        const int gg = tid / NC, c = tid - gg * NC;
        float a = bro[c];
#pragma unroll 8
        for (int k = 0; k < 128; k++) a = fmaf(sx[gg][k], Wro[k * NC + c], a);
        out[(g0 + gg) * NC + c] = a;
    }
}

// -------------------------------------------------------------------------
extern "C" void kernel_launch(void* const* d_in, const int* in_sizes, int n_in,
                              void* d_out, int out_size)
{
    const float* diag0 = (const float*)d_in[0];
    const float* diag1 = (const float*)d_in[1];
    const float* gf    = (const float*)d_in[2];
    const float* theta = (const float*)d_in[3];
    const float* Ww0   = (const float*)d_in[4];
    const float* bw0   = (const float*)d_in[5];
    const float* Ww1   = (const float*)d_in[6];
    const float* bw1   = (const float*)d_in[7];
    const float* Wwo   = (const float*)d_in[8];
    const float* bwo   = (const float*)d_in[9];
    const float* Wr0   = (const float*)d_in[10];
    const float* br0   = (const float*)d_in[11];
    const float* Wr1   = (const float*)d_in[12];
    const float* br1   = (const float*)d_in[13];
    const float* Wro   = (const float*)d_in[14];
    const float* bro   = (const float*)d_in[15];
    const int*   batch0 = (const int*)d_in[16];
    const int*   batch1 = (const int*)d_in[17];

    const int dynsmem = 4 * 32 * 32 * (int)sizeof(float);   // 16 KB H staging

    weight_mlp_kernel<<<2 * B_GR, 128, dynsmem>>>(diag0, diag1,
                                                  Ww0, bw0, Ww1, bw1, Wwo, bwo);
    gauss_pool_kernel<<<2 * B_GR, 128>>>(diag0, diag1, batch0, batch1, theta);
    final_mlp_kernel<<<B_GR / GPB, 128>>>(gf, Wr0, br0, Wr1, br1, Wro, bro,
                                          (float*)d_out);
}

// round 6
// speedup vs baseline: 7.0334x; 2.2818x over previous
#include <cuda_runtime.h>
#include <cuda_bf16.h>
#include <cstdint>

#define T_PTS 524288
#define B_GR  1024
#define NC    10

typedef unsigned long long u64;

// staging buffers
__device__ float g_w[2 * T_PTS];       // per-point sigmoid weights
__device__ float g_X[B_GR * 128];      // pooled features (v0 | v1)

__device__ __forceinline__ uint32_t to_tf32(float x) {
    uint32_t r;
    asm("cvt.rna.tf32.f32 %0, %1;" : "=r"(r) : "f"(x));
    return r;
}

// -------------------------------------------------------------------------
// Kernel W: weight MLP with mma.sync m16n8k8 tf32 (fallback HMMA on sm_103).
// Per warp-tile (32 pts x 64 outs): layer-1 computed straight into A
// fragments; B = W1 fragment pairs pre-packed in smem; bias in accumulators;
// epilogue relu.Wo + shfl reduce + sigmoid. Warps independent.
// -------------------------------------------------------------------------
__global__ __launch_bounds__(128) void weight_mlp_mma(
    const float* __restrict__ diag0, const float* __restrict__ diag1,
    const float* __restrict__ Ww0, const float* __restrict__ bw0,
    const float* __restrict__ Ww1, const float* __restrict__ bw1,
    const float* __restrict__ Wwo, const float* __restrict__ bwo)
{
    __shared__ __align__(16) u64    sBf[2048];   // [kt*8+nt][lane] = {b0,b1}
    __shared__ __align__(16) float4 sC[64];      // {W0x, W0y, b0w, 0}
    __shared__ __align__(8)  float  sB1[64];     // layer-2 bias
    __shared__ __align__(8)  float  sWo[64];     // output weights

    const int tid  = threadIdx.x;
    const int lane = tid & 31;
    const int wrp  = tid >> 5;
    const int tig  = lane & 3;        // threadID_in_group
    const int gid  = lane >> 2;       // groupID

    // ---- stage fragments / constants ----
    for (int e = tid; e < 2048; e += 128) {
        const int combo = e >> 5, ln = e & 31;
        const int kt = combo >> 3, nt = combo & 7;
        const int tg = ln & 3, gd = ln >> 2;
        const int k0 = kt * 8 + tg, n = nt * 8 + gd;
        const uint32_t lo = to_tf32(Ww1[k0 * 64 + n]);
        const uint32_t hi = to_tf32(Ww1[(k0 + 4) * 64 + n]);
        sBf[e] = ((u64)hi << 32) | (u64)lo;
    }
    if (tid < 64) {
        sC[tid]  = make_float4(Ww0[tid], Ww0[64 + tid], bw0[tid], 0.f);
        sB1[tid] = bw1[tid];
        sWo[tid] = Wwo[tid];
    }
    const float bwo0 = bwo[0];
    __syncthreads();

    const int branch = blockIdx.x >> 10;
    const float2* p2 = (const float2*)(branch ? diag1 : diag0);
    float* wout      = g_w + branch * T_PTS;
    const int wbase  = (blockIdx.x & 1023) * 512 + wrp * 128;

#pragma unroll 1
    for (int t = 0; t < 4; t++) {
        const int tbase = wbase + t * 32;
        const float2 p  = p2[tbase + lane];

        float px[4], py[4];
#pragma unroll
        for (int m = 0; m < 4; m++) {
            px[m] = __shfl_sync(0xffffffffu, p.x, gid + 8 * m);
            py[m] = __shfl_sync(0xffffffffu, p.y, gid + 8 * m);
        }

        // acc init = layer-2 bias
        float acc[2][8][4];
#pragma unroll
        for (int nt = 0; nt < 8; nt++) {
            const float2 bb = *(const float2*)&sB1[nt * 8 + 2 * tig];
#pragma unroll
            for (int mt = 0; mt < 2; mt++) {
                acc[mt][nt][0] = bb.x; acc[mt][nt][1] = bb.y;
                acc[mt][nt][2] = bb.x; acc[mt][nt][3] = bb.y;
            }
        }

#pragma unroll
        for (int kt = 0; kt < 8; kt++) {
            const float4 c0 = sC[kt * 8 + tig];
            const float4 c1 = sC[kt * 8 + tig + 4];
            uint32_t hv0[4], hv1[4];
#pragma unroll
            for (int m = 0; m < 4; m++) {
                hv0[m] = to_tf32(fmaxf(fmaf(px[m], c0.x,
                                       fmaf(py[m], c0.y, c0.z)), 0.f));
                hv1[m] = to_tf32(fmaxf(fmaf(px[m], c1.x,
                                       fmaf(py[m], c1.y, c1.z)), 0.f));
            }
#pragma unroll
            for (int nt = 0; nt < 8; nt++) {
                const u64 bu = sBf[(kt * 8 + nt) * 32 + lane];
                const uint32_t b0 = (uint32_t)bu, b1 = (uint32_t)(bu >> 32);
                asm volatile(
                    "mma.sync.aligned.m16n8k8.row.col.f32.tf32.tf32.f32 "
                    "{%0,%1,%2,%3}, {%4,%5,%6,%7}, {%8,%9}, {%0,%1,%2,%3};"
                    : "+f"(acc[0][nt][0]), "+f"(acc[0][nt][1]),
                      "+f"(acc[0][nt][2]), "+f"(acc[0][nt][3])
                    : "r"(hv0[0]), "r"(hv0[1]), "r"(hv1[0]), "r"(hv1[1]),
                      "r"(b0), "r"(b1));
                asm volatile(
                    "mma.sync.aligned.m16n8k8.row.col.f32.tf32.tf32.f32 "
                    "{%0,%1,%2,%3}, {%4,%5,%6,%7}, {%8,%9}, {%0,%1,%2,%3};"
                    : "+f"(acc[1][nt][0]), "+f"(acc[1][nt][1]),
                      "+f"(acc[1][nt][2]), "+f"(acc[1][nt][3])
                    : "r"(hv0[2]), "r"(hv0[3]), "r"(hv1[2]), "r"(hv1[3]),
                      "r"(b0), "r"(b1));
            }
        }

        // ---- epilogue: s[m] = sum_o relu(z)*Wo for pt gid+8m ----
        float s[4] = {0.f, 0.f, 0.f, 0.f};
#pragma unroll
        for (int nt = 0; nt < 8; nt++) {
            const float2 wo = *(const float2*)&sWo[nt * 8 + 2 * tig];
#pragma unroll
            for (int mt = 0; mt < 2; mt++) {
                s[2*mt]   = fmaf(fmaxf(acc[mt][nt][0], 0.f), wo.x, s[2*mt]);
                s[2*mt]   = fmaf(fmaxf(acc[mt][nt][1], 0.f), wo.y, s[2*mt]);
                s[2*mt+1] = fmaf(fmaxf(acc[mt][nt][2], 0.f), wo.x, s[2*mt+1]);
                s[2*mt+1] = fmaf(fmaxf(acc[mt][nt][3], 0.f), wo.y, s[2*mt+1]);
            }
        }
#pragma unroll
        for (int m = 0; m < 4; m++) {
            s[m] += __shfl_xor_sync(0xffffffffu, s[m], 1);
            s[m] += __shfl_xor_sync(0xffffffffu, s[m], 2);
        }
        const float sv = (tig == 0) ? s[0] : (tig == 1) ? s[1]
                       : (tig == 2) ? s[2] : s[3];
        float e, rc;
        asm("ex2.approx.f32 %0, %1;" : "=f"(e)
            : "f"(-1.4426950408889634f * (sv + bwo0)));
        asm("rcp.approx.f32 %0, %1;" : "=f"(rc) : "f"(1.f + e));
        wout[tbase + gid + 8 * tig] = rc;
    }
}

// -------------------------------------------------------------------------
// Kernel G: gaussian rep + weighted pooling, q-per-lane; point broadcast
// via one LDS.128 per point (staged float4 {px,py,c,w}) instead of 4 shfl.
// -------------------------------------------------------------------------
__global__ __launch_bounds__(128) void gauss_pool_kernel(
    const float* __restrict__ diag0, const float* __restrict__ diag1,
    const int* __restrict__ batch0, const int* __restrict__ batch1,
    const float* __restrict__ theta)
{
    __shared__ __align__(16) float4 sP[4][32];
    __shared__ float sRed[4][64];

    const int bid    = blockIdx.x;
    const int branch = bid >> 10;
    const int g      = bid & (B_GR - 1);
    const int tid    = threadIdx.x;
    const int lane   = tid & 31, wrp = tid >> 5;
    const float2* p2  = (const float2*)(branch ? diag1 : diag0);
    const int* batch  = branch ? batch1 : batch0;
    const float* wbuf = g_w + branch * T_PTS;

    const float K2 = -72.13475204444817f;   // -50 * log2(e)  (sigma=0.1)
    const float M2 = 144.26950408889634f;   // +100 * log2(e)
    const float2 t0 = ((const float2*)theta)[lane];
    const float2 t1 = ((const float2*)theta)[lane + 32];
    const float gx0 = M2 * t0.x, gy0 = M2 * t0.y;
    const float ga0 = K2 * fmaf(t0.x, t0.x, t0.y * t0.y);
    const float gx1 = M2 * t1.x, gy1 = M2 * t1.y;
    const float ga1 = K2 * fmaf(t1.x, t1.x, t1.y * t1.y);

    int lo = 0, hi = T_PTS;
    while (lo < hi) { int m = (lo + hi) >> 1; if (batch[m] < g) lo = m + 1; else hi = m; }
    const int start = lo;
    hi = T_PTS;
    while (lo < hi) { int m = (lo + hi) >> 1; if (batch[m] < g + 1) lo = m + 1; else hi = m; }
    const int end = lo;

    float acc0 = 0.f, acc1 = 0.f;

    for (int base = start + wrp * 32; base < end; base += 128) {
        const int n = min(32, end - base);
        float2 p = make_float2(0.f, 0.f);
        float  w = 0.f;
        if (lane < n) { p = p2[base + lane]; w = wbuf[base + lane]; }
        sP[wrp][lane] = make_float4(p.x, p.y,
                                    K2 * fmaf(p.x, p.x, p.y * p.y), w);
        __syncwarp();

        if (n == 32) {
#pragma unroll 8
            for (int j = 0; j < 32; j++) {
                const float4 q = sP[wrp][j];
                float a0 = fmaf(q.x, gx0, fmaf(q.y, gy0, ga0 + q.z));
                float a1 = fmaf(q.x, gx1, fmaf(q.y, gy1, ga1 + q.z));
                float r0, r1;
                asm("ex2.approx.f32 %0, %1;" : "=f"(r0) : "f"(a0));
                asm("ex2.approx.f32 %0, %1;" : "=f"(r1) : "f"(a1));
                acc0 = fmaf(q.w, r0, acc0);
                acc1 = fmaf(q.w, r1, acc1);
            }
        } else {
            for (int j = 0; j < n; j++) {
                const float4 q = sP[wrp][j];
                float a0 = fmaf(q.x, gx0, fmaf(q.y, gy0, ga0 + q.z));
                float a1 = fmaf(q.x, gx1, fmaf(q.y, gy1, ga1 + q.z));
                float r0, r1;
                asm("ex2.approx.f32 %0, %1;" : "=f"(r0) : "f"(a0));
                asm("ex2.approx.f32 %0, %1;" : "=f"(r1) : "f"(a1));
                acc0 = fmaf(q.w, r0, acc0);
                acc1 = fmaf(q.w, r1, acc1);
            }
        }
        __syncwarp();
    }

    sRed[wrp][lane]      = acc0;
    sRed[wrp][lane + 32] = acc1;
    __syncthreads();
    if (tid < 64)
        g_X[g * 128 + branch * 64 + tid]
            = sRed[0][tid] + sRed[1][tid] + sRed[2][tid] + sRed[3][tid];
}

// -------------------------------------------------------------------------
// Kernel B: final MLP [B,144] -> relu 128 -> relu 128 -> 10.
// -------------------------------------------------------------------------
#define GPB 2
__global__ __launch_bounds__(128) void final_mlp_kernel(
    const float* __restrict__ gf,
    const float* __restrict__ Wr0, const float* __restrict__ br0,
    const float* __restrict__ Wr1, const float* __restrict__ br1,
    const float* __restrict__ Wro, const float* __restrict__ bro,
    float* __restrict__ out)
{
    __shared__ float sx[GPB][144];
    __shared__ float sh[GPB][128];
    const int g0  = blockIdx.x * GPB;
    const int tid = threadIdx.x;

    for (int idx = tid; idx < GPB * 144; idx += 128) {
        int gg = idx / 144, c = idx - gg * 144;
        sx[gg][c] = (c < 128) ? g_X[(g0 + gg) * 128 + c]
                              : gf[(g0 + gg) * 16 + (c - 128)];
    }
    __syncthreads();

    {
        float a0 = br0[tid], a1 = a0;
#pragma unroll 8
        for (int i = 0; i < 144; i++) {
            const float wv = Wr0[i * 128 + tid];
            a0 = fmaf(sx[0][i], wv, a0);
            a1 = fmaf(sx[1][i], wv, a1);
        }
        sh[0][tid] = fmaxf(a0, 0.f);
        sh[1][tid] = fmaxf(a1, 0.f);
    }
    __syncthreads();

    {
        float a0 = br1[tid], a1 = a0;
#pragma unroll 8
        for (int i = 0; i < 128; i++) {
            const float wv = Wr1[i * 128 + tid];
            a0 = fmaf(sh[0][i], wv, a0);
            a1 = fmaf(sh[1][i], wv, a1);
        }
        sx[0][tid] = fmaxf(a0, 0.f);
        sx[1][tid] = fmaxf(a1, 0.f);
    }
    __syncthreads();

    if (tid < GPB * NC) {
        const int gg = tid / NC, c = tid - gg * NC;
        float a = bro[c];
#pragma unroll 8
        for (int k = 0; k < 128; k++) a = fmaf(sx[gg][k], Wro[k * NC + c], a);
        out[(g0 + gg) * NC + c] = a;
    }
}

// -------------------------------------------------------------------------
extern "C" void kernel_launch(void* const* d_in, const int* in_sizes, int n_in,
                              void* d_out, int out_size)
{
    const float* diag0 = (const float*)d_in[0];
    const float* diag1 = (const float*)d_in[1];
    const float* gf    = (const float*)d_in[2];
    const float* theta = (const float*)d_in[3];
    const float* Ww0   = (const float*)d_in[4];
    const float* bw0   = (const float*)d_in[5];
    const float* Ww1   = (const float*)d_in[6];
    const float* bw1   = (const float*)d_in[7];
    const float* Wwo   = (const float*)d_in[8];
    const float* bwo   = (const float*)d_in[9];
    const float* Wr0   = (const float*)d_in[10];
    const float* br0   = (const float*)d_in[11];
    const float* Wr1   = (const float*)d_in[12];
    const float* br1   = (const float*)d_in[13];
    const float* Wro   = (const float*)d_in[14];
    const float* bro   = (const float*)d_in[15];
    const int*   batch0 = (const int*)d_in[16];
    const int*   batch1 = (const int*)d_in[17];

    weight_mlp_mma<<<2 * B_GR, 128>>>(diag0, diag1,
                                      Ww0, bw0, Ww1, bw1, Wwo, bwo);
    gauss_pool_kernel<<<2 * B_GR, 128>>>(diag0, diag1, batch0, batch1, theta);
    final_mlp_kernel<<<B_GR / GPB, 128>>>(gf, Wr0, br0, Wr1, br1, Wro, bro,
                                          (float*)d_out);
}

// round 7
// speedup vs baseline: 8.4746x; 1.2049x over previous
#include <cuda_runtime.h>
#include <cuda_bf16.h>
#include <cstdint>

#define T_PTS 524288
#define B_GR  1024
#define NC    10

typedef unsigned long long u64;

// staging buffers
__device__ float g_w[2 * T_PTS];       // per-point sigmoid weights
__device__ float g_X[B_GR * 128];      // pooled features (v0 | v1)

__device__ __forceinline__ uint32_t pack_bf16x2(float lowv, float highv) {
    uint32_t r;
    asm("cvt.rn.bf16x2.f32 %0, %1, %2;" : "=r"(r) : "f"(highv), "f"(lowv));
    return r;
}

// -------------------------------------------------------------------------
// Kernel W: weight MLP with mma.sync m16n8k16 bf16 (fallback HMMA on sm_103).
// Per warp-tile (32 pts x 64 outs): layer-1 computed straight into bf16x2 A
// fragments; B = W1 fragment pairs pre-packed in smem (8KB); bias in
// accumulators; epilogue relu.Wo + shfl reduce + sigmoid. Warps independent.
// -------------------------------------------------------------------------
__global__ __launch_bounds__(128) void weight_mlp_mma(
    const float* __restrict__ diag0, const float* __restrict__ diag1,
    const float* __restrict__ Ww0, const float* __restrict__ bw0,
    const float* __restrict__ Ww1, const float* __restrict__ bw1,
    const float* __restrict__ Wwo, const float* __restrict__ bwo)
{
    __shared__ __align__(16) u64    sBf[1024];   // [kt*8+nt][lane] = {b0,b1}
    __shared__ __align__(16) float4 sC[64];      // {W0x, W0y, b0w, 0}
    __shared__ __align__(8)  float  sB1[64];     // layer-2 bias
    __shared__ __align__(8)  float  sWo[64];     // output weights

    const int tid  = threadIdx.x;
    const int lane = tid & 31;
    const int wrp  = tid >> 5;
    const int tig  = lane & 3;        // threadID_in_group
    const int gid  = lane >> 2;       // groupID

    // ---- stage B fragments (bf16, m16n8k16 col-major layout) ----
    for (int e = tid; e < 1024; e += 128) {
        const int combo = e >> 5, ln = e & 31;
        const int kt = combo >> 3, nt = combo & 7;
        const int tg = ln & 3, gd = ln >> 2;
        const int k0 = kt * 16 + 2 * tg;
        const int n  = nt * 8 + gd;
        const uint32_t lo = pack_bf16x2(Ww1[k0 * 64 + n],       Ww1[(k0 + 1) * 64 + n]);
        const uint32_t hi = pack_bf16x2(Ww1[(k0 + 8) * 64 + n], Ww1[(k0 + 9) * 64 + n]);
        sBf[e] = ((u64)hi << 32) | (u64)lo;
    }
    if (tid < 64) {
        sC[tid]  = make_float4(Ww0[tid], Ww0[64 + tid], bw0[tid], 0.f);
        sB1[tid] = bw1[tid];
        sWo[tid] = Wwo[tid];
    }
    const float bwo0 = bwo[0];
    __syncthreads();

    const int branch = blockIdx.x >> 10;
    const float2* p2 = (const float2*)(branch ? diag1 : diag0);
    float* wout      = g_w + branch * T_PTS;
    const int wbase  = (blockIdx.x & 1023) * 512 + wrp * 128;

#pragma unroll 1
    for (int t = 0; t < 4; t++) {
        const int tbase = wbase + t * 32;
        const float2 p  = p2[tbase + lane];

        float px[4], py[4];
#pragma unroll
        for (int m = 0; m < 4; m++) {
            px[m] = __shfl_sync(0xffffffffu, p.x, gid + 8 * m);
            py[m] = __shfl_sync(0xffffffffu, p.y, gid + 8 * m);
        }

        // acc init = layer-2 bias
        float acc[2][8][4];
#pragma unroll
        for (int nt = 0; nt < 8; nt++) {
            const float2 bb = *(const float2*)&sB1[nt * 8 + 2 * tig];
#pragma unroll
            for (int mt = 0; mt < 2; mt++) {
                acc[mt][nt][0] = bb.x; acc[mt][nt][1] = bb.y;
                acc[mt][nt][2] = bb.x; acc[mt][nt][3] = bb.y;
            }
        }

#pragma unroll
        for (int kt = 0; kt < 4; kt++) {
            const int ka = kt * 16 + 2 * tig;
            const float4 ca = sC[ka];
            const float4 cb = sC[ka + 1];
            const float4 cc = sC[ka + 8];
            const float4 cd = sC[ka + 9];
            uint32_t pLo[4], pHi[4];
#pragma unroll
            for (int m = 0; m < 4; m++) {
                const float hA = fmaxf(fmaf(px[m], ca.x, fmaf(py[m], ca.y, ca.z)), 0.f);
                const float hB = fmaxf(fmaf(px[m], cb.x, fmaf(py[m], cb.y, cb.z)), 0.f);
                const float hC = fmaxf(fmaf(px[m], cc.x, fmaf(py[m], cc.y, cc.z)), 0.f);
                const float hD = fmaxf(fmaf(px[m], cd.x, fmaf(py[m], cd.y, cd.z)), 0.f);
                pLo[m] = pack_bf16x2(hA, hB);
                pHi[m] = pack_bf16x2(hC, hD);
            }
#pragma unroll
            for (int nt = 0; nt < 8; nt++) {
                const u64 bu = sBf[(kt * 8 + nt) * 32 + lane];
                const uint32_t b0 = (uint32_t)bu, b1 = (uint32_t)(bu >> 32);
                asm volatile(
                    "mma.sync.aligned.m16n8k16.row.col.f32.bf16.bf16.f32 "
                    "{%0,%1,%2,%3}, {%4,%5,%6,%7}, {%8,%9}, {%0,%1,%2,%3};"
                    : "+f"(acc[0][nt][0]), "+f"(acc[0][nt][1]),
                      "+f"(acc[0][nt][2]), "+f"(acc[0][nt][3])
                    : "r"(pLo[0]), "r"(pLo[1]), "r"(pHi[0]), "r"(pHi[1]),
                      "r"(b0), "r"(b1));
                asm volatile(
                    "mma.sync.aligned.m16n8k16.row.col.f32.bf16.bf16.f32 "
                    "{%0,%1,%2,%3}, {%4,%5,%6,%7}, {%8,%9}, {%0,%1,%2,%3};"
                    : "+f"(acc[1][nt][0]), "+f"(acc[1][nt][1]),
                      "+f"(acc[1][nt][2]), "+f"(acc[1][nt][3])
                    : "r"(pLo[2]), "r"(pLo[3]), "r"(pHi[2]), "r"(pHi[3]),
                      "r"(b0), "r"(b1));
            }
        }

        // ---- epilogue: s[m] = sum_o relu(z)*Wo for pt gid+8m ----
        float s[4] = {0.f, 0.f, 0.f, 0.f};
#pragma unroll
        for (int nt = 0; nt < 8; nt++) {
            const float2 wo = *(const float2*)&sWo[nt * 8 + 2 * tig];
#pragma unroll
            for (int mt = 0; mt < 2; mt++) {
                s[2*mt]   = fmaf(fmaxf(acc[mt][nt][0], 0.f), wo.x, s[2*mt]);
                s[2*mt]   = fmaf(fmaxf(acc[mt][nt][1], 0.f), wo.y, s[2*mt]);
                s[2*mt+1] = fmaf(fmaxf(acc[mt][nt][2], 0.f), wo.x, s[2*mt+1]);
                s[2*mt+1] = fmaf(fmaxf(acc[mt][nt][3], 0.f), wo.y, s[2*mt+1]);
            }
        }
#pragma unroll
        for (int m = 0; m < 4; m++) {
            s[m] += __shfl_xor_sync(0xffffffffu, s[m], 1);
            s[m] += __shfl_xor_sync(0xffffffffu, s[m], 2);
        }
        const float sv = (tig == 0) ? s[0] : (tig == 1) ? s[1]
                       : (tig == 2) ? s[2] : s[3];
        float e, rc;
        asm("ex2.approx.f32 %0, %1;" : "=f"(e)
            : "f"(-1.4426950408889634f * (sv + bwo0)));
        asm("rcp.approx.f32 %0, %1;" : "=f"(rc) : "f"(1.f + e));
        wout[tbase + gid + 8 * tig] = rc;
    }
}

// -------------------------------------------------------------------------
// Kernel G: gaussian rep + weighted pooling, q-per-lane; point broadcast
// via one LDS.128 per point (staged float4 {px,py,c,w}).
// -------------------------------------------------------------------------
__global__ __launch_bounds__(128) void gauss_pool_kernel(
    const float* __restrict__ diag0, const float* __restrict__ diag1,
    const int* __restrict__ batch0, const int* __restrict__ batch1,
    const float* __restrict__ theta)
{
    __shared__ __align__(16) float4 sP[4][32];
    __shared__ float sRed[4][64];

    const int bid    = blockIdx.x;
    const int branch = bid >> 10;
    const int g      = bid & (B_GR - 1);
    const int tid    = threadIdx.x;
    const int lane   = tid & 31, wrp = tid >> 5;
    const float2* p2  = (const float2*)(branch ? diag1 : diag0);
    const int* batch  = branch ? batch1 : batch0;
    const float* wbuf = g_w + branch * T_PTS;

    const float K2 = -72.13475204444817f;   // -50 * log2(e)  (sigma=0.1)
    const float M2 = 144.26950408889634f;   // +100 * log2(e)
    const float2 t0 = ((const float2*)theta)[lane];
    const float2 t1 = ((const float2*)theta)[lane + 32];
    const float gx0 = M2 * t0.x, gy0 = M2 * t0.y;
    const float ga0 = K2 * fmaf(t0.x, t0.x, t0.y * t0.y);
    const float gx1 = M2 * t1.x, gy1 = M2 * t1.y;
    const float ga1 = K2 * fmaf(t1.x, t1.x, t1.y * t1.y);

    int lo = 0, hi = T_PTS;
    while (lo < hi) { int m = (lo + hi) >> 1; if (batch[m] < g) lo = m + 1; else hi = m; }
    const int start = lo;
    hi = T_PTS;
    while (lo < hi) { int m = (lo + hi) >> 1; if (batch[m] < g + 1) lo = m + 1; else hi = m; }
    const int end = lo;

    float acc0 = 0.f, acc1 = 0.f;

    for (int base = start + wrp * 32; base < end; base += 128) {
        const int n = min(32, end - base);
        float2 p = make_float2(0.f, 0.f);
        float  w = 0.f;
        if (lane < n) { p = p2[base + lane]; w = wbuf[base + lane]; }
        sP[wrp][lane] = make_float4(p.x, p.y,
                                    K2 * fmaf(p.x, p.x, p.y * p.y), w);
        __syncwarp();

        if (n == 32) {
#pragma unroll 8
            for (int j = 0; j < 32; j++) {
                const float4 q = sP[wrp][j];
                float a0 = fmaf(q.x, gx0, fmaf(q.y, gy0, ga0 + q.z));
                float a1 = fmaf(q.x, gx1, fmaf(q.y, gy1, ga1 + q.z));
                float r0, r1;
                asm("ex2.approx.f32 %0, %1;" : "=f"(r0) : "f"(a0));
                asm("ex2.approx.f32 %0, %1;" : "=f"(r1) : "f"(a1));
                acc0 = fmaf(q.w, r0, acc0);
                acc1 = fmaf(q.w, r1, acc1);
            }
        } else {
            for (int j = 0; j < n; j++) {
                const float4 q = sP[wrp][j];
                float a0 = fmaf(q.x, gx0, fmaf(q.y, gy0, ga0 + q.z));
                float a1 = fmaf(q.x, gx1, fmaf(q.y, gy1, ga1 + q.z));
                float r0, r1;
                asm("ex2.approx.f32 %0, %1;" : "=f"(r0) : "f"(a0));
                asm("ex2.approx.f32 %0, %1;" : "=f"(r1) : "f"(a1));
                acc0 = fmaf(q.w, r0, acc0);
                acc1 = fmaf(q.w, r1, acc1);
            }
        }
        __syncwarp();
    }

    sRed[wrp][lane]      = acc0;
    sRed[wrp][lane + 32] = acc1;
    __syncthreads();
    if (tid < 64)
        g_X[g * 128 + branch * 64 + tid]
            = sRed[0][tid] + sRed[1][tid] + sRed[2][tid] + sRed[3][tid];
}

// -------------------------------------------------------------------------
// Kernel B: final MLP [B,144] -> relu 128 -> relu 128 -> 10.
// -------------------------------------------------------------------------
#define GPB 2
__global__ __launch_bounds__(128) void final_mlp_kernel(
    const float* __restrict__ gf,
    const float* __restrict__ Wr0, const float* __restrict__ br0,
    const float* __restrict__ Wr1, const float* __restrict__ br1,
    const float* __restrict__ Wro, const float* __restrict__ bro,
    float* __restrict__ out)
{
    __shared__ float sx[GPB][144];
    __shared__ float sh[GPB][128];
    const int g0  = blockIdx.x * GPB;
    const int tid = threadIdx.x;

    for (int idx = tid; idx < GPB * 144; idx += 128) {
        int gg = idx / 144, c = idx - gg * 144;
        sx[gg][c] = (c < 128) ? g_X[(g0 + gg) * 128 + c]
                              : gf[(g0 + gg) * 16 + (c - 128)];
    }
    __syncthreads();

    {
        float a0 = br0[tid], a1 = a0;
#pragma unroll 8
        for (int i = 0; i < 144; i++) {
            const float wv = Wr0[i * 128 + tid];
            a0 = fmaf(sx[0][i], wv, a0);
            a1 = fmaf(sx[1][i], wv, a1);
        }
        sh[0][tid] = fmaxf(a0, 0.f);
        sh[1][tid] = fmaxf(a1, 0.f);
    }
    __syncthreads();

    {
        float a0 = br1[tid], a1 = a0;
#pragma unroll 8
        for (int i = 0; i < 128; i++) {
            const float wv = Wr1[i * 128 + tid];
            a0 = fmaf(sh[0][i], wv, a0);
            a1 = fmaf(sh[1][i], wv, a1);
        }
        sx[0][tid] = fmaxf(a0, 0.f);
        sx[1][tid] = fmaxf(a1, 0.f);
    }
    __syncthreads();

    if (tid < GPB * NC) {
        const int gg = tid / NC, c = tid - gg * NC;
        float a = bro[c];
#pragma unroll 8
        for (int k = 0; k < 128; k++) a = fmaf(sx[gg][k], Wro[k * NC + c], a);
        out[(g0 + gg) * NC + c] = a;
    }
}

// -------------------------------------------------------------------------
extern "C" void kernel_launch(void* const* d_in, const int* in_sizes, int n_in,
                              void* d_out, int out_size)
{
    const float* diag0 = (const float*)d_in[0];
    const float* diag1 = (const float*)d_in[1];
    const float* gf    = (const float*)d_in[2];
    const float* theta = (const float*)d_in[3];
    const float* Ww0   = (const float*)d_in[4];
    const float* bw0   = (const float*)d_in[5];
    const float* Ww1   = (const float*)d_in[6];
    const float* bw1   = (const float*)d_in[7];
    const float* Wwo   = (const float*)d_in[8];
    const float* bwo   = (const float*)d_in[9];
    const float* Wr0   = (const float*)d_in[10];
    const float* br0   = (const float*)d_in[11];
    const float* Wr1   = (const float*)d_in[12];
    const float* br1   = (const float*)d_in[13];
    const float* Wro   = (const float*)d_in[14];
    const float* bro   = (const float*)d_in[15];
    const int*   batch0 = (const int*)d_in[16];
    const int*   batch1 = (const int*)d_in[17];

    weight_mlp_mma<<<2 * B_GR, 128>>>(diag0, diag1,
                                      Ww0, bw0, Ww1, bw1, Wwo, bwo);
    gauss_pool_kernel<<<2 * B_GR, 128>>>(diag0, diag1, batch0, batch1, theta);
    final_mlp_kernel<<<B_GR / GPB, 128>>>(gf, Wr0, br0, Wr1, br1, Wro, bro,
                                          (float*)d_out);
}

// round 8
// speedup vs baseline: 8.8693x; 1.0466x over previous
#include <cuda_runtime.h>
#include <cuda_bf16.h>
#include <cstdint>

#define T_PTS 524288
#define B_GR  1024
#define NC    10

typedef unsigned long long u64;

// staging buffers
__device__ float g_w[2 * T_PTS];         // per-point sigmoid weights
__device__ float g_X[B_GR * 128];        // pooled features (v0 | v1)
__device__ int   g_segs[2][B_GR + 1];    // segment bounds per branch

__device__ __forceinline__ uint32_t pack_bf16x2(float lowv, float highv) {
    uint32_t r;
    asm("cvt.rn.bf16x2.f32 %0, %1, %2;" : "=r"(r) : "f"(highv), "f"(lowv));
    return r;
}

// -------------------------------------------------------------------------
// Kernel S: segment bounds from sorted batch ids (one pass, no binary search
// left in the hot kernels).
// -------------------------------------------------------------------------
__global__ __launch_bounds__(256) void seg_bounds_kernel(
    const int* __restrict__ batch0, const int* __restrict__ batch1)
{
    const int i  = blockIdx.x * 256 + threadIdx.x;
    const int br = blockIdx.y;
    if (i >= T_PTS) return;
    const int* b = br ? batch1 : batch0;
    int* s = g_segs[br];
    const int cur  = b[i];
    const int prev = (i == 0) ? -1 : b[i - 1];
    for (int g = prev + 1; g <= cur; g++) s[g] = i;
    if (i == T_PTS - 1)
        for (int g = cur + 1; g <= B_GR; g++) s[g] = T_PTS;
}

// -------------------------------------------------------------------------
// Kernel W: weight MLP with mma.sync m16n8k16 bf16 (fallback HMMA on sm_103).
// -------------------------------------------------------------------------
__global__ __launch_bounds__(128) void weight_mlp_mma(
    const float* __restrict__ diag0, const float* __restrict__ diag1,
    const float* __restrict__ Ww0, const float* __restrict__ bw0,
    const float* __restrict__ Ww1, const float* __restrict__ bw1,
    const float* __restrict__ Wwo, const float* __restrict__ bwo)
{
    __shared__ __align__(16) u64    sBf[1024];   // [kt*8+nt][lane] = {b0,b1}
    __shared__ __align__(16) float4 sC[64];      // {W0x, W0y, b0w, 0}
    __shared__ __align__(8)  float  sB1[64];     // layer-2 bias
    __shared__ __align__(8)  float  sWo[64];     // output weights

    const int tid  = threadIdx.x;
    const int lane = tid & 31;
    const int wrp  = tid >> 5;
    const int tig  = lane & 3;
    const int gid  = lane >> 2;

    for (int e = tid; e < 1024; e += 128) {
        const int combo = e >> 5, ln = e & 31;
        const int kt = combo >> 3, nt = combo & 7;
        const int tg = ln & 3, gd = ln >> 2;
        const int k0 = kt * 16 + 2 * tg;
        const int n  = nt * 8 + gd;
        const uint32_t lo = pack_bf16x2(Ww1[k0 * 64 + n],       Ww1[(k0 + 1) * 64 + n]);
        const uint32_t hi = pack_bf16x2(Ww1[(k0 + 8) * 64 + n], Ww1[(k0 + 9) * 64 + n]);
        sBf[e] = ((u64)hi << 32) | (u64)lo;
    }
    if (tid < 64) {
        sC[tid]  = make_float4(Ww0[tid], Ww0[64 + tid], bw0[tid], 0.f);
        sB1[tid] = bw1[tid];
        sWo[tid] = Wwo[tid];
    }
    const float bwo0 = bwo[0];
    __syncthreads();

    const int branch = blockIdx.x >> 10;
    const float2* p2 = (const float2*)(branch ? diag1 : diag0);
    float* wout      = g_w + branch * T_PTS;
    const int wbase  = (blockIdx.x & 1023) * 512 + wrp * 128;

#pragma unroll 1
    for (int t = 0; t < 4; t++) {
        const int tbase = wbase + t * 32;
        const float2 p  = p2[tbase + lane];

        float px[4], py[4];
#pragma unroll
        for (int m = 0; m < 4; m++) {
            px[m] = __shfl_sync(0xffffffffu, p.x, gid + 8 * m);
            py[m] = __shfl_sync(0xffffffffu, p.y, gid + 8 * m);
        }

        float acc[2][8][4];
#pragma unroll
        for (int nt = 0; nt < 8; nt++) {
            const float2 bb = *(const float2*)&sB1[nt * 8 + 2 * tig];
#pragma unroll
            for (int mt = 0; mt < 2; mt++) {
                acc[mt][nt][0] = bb.x; acc[mt][nt][1] = bb.y;
                acc[mt][nt][2] = bb.x; acc[mt][nt][3] = bb.y;
            }
        }

#pragma unroll
        for (int kt = 0; kt < 4; kt++) {
            const int ka = kt * 16 + 2 * tig;
            const float4 ca = sC[ka];
            const float4 cb = sC[ka + 1];
            const float4 cc = sC[ka + 8];
            const float4 cd = sC[ka + 9];
            uint32_t pLo[4], pHi[4];
#pragma unroll
            for (int m = 0; m < 4; m++) {
                const float hA = fmaxf(fmaf(px[m], ca.x, fmaf(py[m], ca.y, ca.z)), 0.f);
                const float hB = fmaxf(fmaf(px[m], cb.x, fmaf(py[m], cb.y, cb.z)), 0.f);
                const float hC = fmaxf(fmaf(px[m], cc.x, fmaf(py[m], cc.y, cc.z)), 0.f);
                const float hD = fmaxf(fmaf(px[m], cd.x, fmaf(py[m], cd.y, cd.z)), 0.f);
                pLo[m] = pack_bf16x2(hA, hB);
                pHi[m] = pack_bf16x2(hC, hD);
            }
#pragma unroll
            for (int nt = 0; nt < 8; nt++) {
                const u64 bu = sBf[(kt * 8 + nt) * 32 + lane];
                const uint32_t b0 = (uint32_t)bu, b1 = (uint32_t)(bu >> 32);
                asm volatile(
                    "mma.sync.aligned.m16n8k16.row.col.f32.bf16.bf16.f32 "
                    "{%0,%1,%2,%3}, {%4,%5,%6,%7}, {%8,%9}, {%0,%1,%2,%3};"
                    : "+f"(acc[0][nt][0]), "+f"(acc[0][nt][1]),
                      "+f"(acc[0][nt][2]), "+f"(acc[0][nt][3])
                    : "r"(pLo[0]), "r"(pLo[1]), "r"(pHi[0]), "r"(pHi[1]),
                      "r"(b0), "r"(b1));
                asm volatile(
                    "mma.sync.aligned.m16n8k16.row.col.f32.bf16.bf16.f32 "
                    "{%0,%1,%2,%3}, {%4,%5,%6,%7}, {%8,%9}, {%0,%1,%2,%3};"
                    : "+f"(acc[1][nt][0]), "+f"(acc[1][nt][1]),
                      "+f"(acc[1][nt][2]), "+f"(acc[1][nt][3])
                    : "r"(pLo[2]), "r"(pLo[3]), "r"(pHi[2]), "r"(pHi[3]),
                      "r"(b0), "r"(b1));
            }
        }

        float s[4] = {0.f, 0.f, 0.f, 0.f};
#pragma unroll
        for (int nt = 0; nt < 8; nt++) {
            const float2 wo = *(const float2*)&sWo[nt * 8 + 2 * tig];
#pragma unroll
            for (int mt = 0; mt < 2; mt++) {
                s[2*mt]   = fmaf(fmaxf(acc[mt][nt][0], 0.f), wo.x, s[2*mt]);
                s[2*mt]   = fmaf(fmaxf(acc[mt][nt][1], 0.f), wo.y, s[2*mt]);
                s[2*mt+1] = fmaf(fmaxf(acc[mt][nt][2], 0.f), wo.x, s[2*mt+1]);
                s[2*mt+1] = fmaf(fmaxf(acc[mt][nt][3], 0.f), wo.y, s[2*mt+1]);
            }
        }
#pragma unroll
        for (int m = 0; m < 4; m++) {
            s[m] += __shfl_xor_sync(0xffffffffu, s[m], 1);
            s[m] += __shfl_xor_sync(0xffffffffu, s[m], 2);
        }
        const float sv = (tig == 0) ? s[0] : (tig == 1) ? s[1]
                       : (tig == 2) ? s[2] : s[3];
        float e, rc;
        asm("ex2.approx.f32 %0, %1;" : "=f"(e)
            : "f"(-1.4426950408889634f * (sv + bwo0)));
        asm("rcp.approx.f32 %0, %1;" : "=f"(rc) : "f"(1.f + e));
        wout[tbase + gid + 8 * tig] = rc;
    }
}

// -------------------------------------------------------------------------
// Kernel G: gaussian rep + weighted pooling, q-per-lane; segment bounds
// read from g_segs (no binary search).
// -------------------------------------------------------------------------
__global__ __launch_bounds__(128) void gauss_pool_kernel(
    const float* __restrict__ diag0, const float* __restrict__ diag1,
    const float* __restrict__ theta)
{
    __shared__ __align__(16) float4 sP[4][32];
    __shared__ float sRed[4][64];

    const int bid    = blockIdx.x;
    const int branch = bid >> 10;
    const int g      = bid & (B_GR - 1);
    const int tid    = threadIdx.x;
    const int lane   = tid & 31, wrp = tid >> 5;
    const float2* p2  = (const float2*)(branch ? diag1 : diag0);
    const float* wbuf = g_w + branch * T_PTS;

    const float K2 = -72.13475204444817f;   // -50 * log2(e)  (sigma=0.1)
    const float M2 = 144.26950408889634f;   // +100 * log2(e)
    const float2 t0 = ((const float2*)theta)[lane];
    const float2 t1 = ((const float2*)theta)[lane + 32];
    const float gx0 = M2 * t0.x, gy0 = M2 * t0.y;
    const float ga0 = K2 * fmaf(t0.x, t0.x, t0.y * t0.y);
    const float gx1 = M2 * t1.x, gy1 = M2 * t1.y;
    const float ga1 = K2 * fmaf(t1.x, t1.x, t1.y * t1.y);

    const int start = g_segs[branch][g];
    const int end   = g_segs[branch][g + 1];

    float acc0 = 0.f, acc1 = 0.f;

    for (int base = start + wrp * 32; base < end; base += 128) {
        const int n = min(32, end - base);
        float2 p = make_float2(0.f, 0.f);
        float  w = 0.f;
        if (lane < n) { p = p2[base + lane]; w = wbuf[base + lane]; }
        sP[wrp][lane] = make_float4(p.x, p.y,
                                    K2 * fmaf(p.x, p.x, p.y * p.y), w);
        __syncwarp();

        if (n == 32) {
#pragma unroll 8
            for (int j = 0; j < 32; j++) {
                const float4 q = sP[wrp][j];
                float a0 = fmaf(q.x, gx0, fmaf(q.y, gy0, ga0 + q.z));
                float a1 = fmaf(q.x, gx1, fmaf(q.y, gy1, ga1 + q.z));
                float r0, r1;
                asm("ex2.approx.f32 %0, %1;" : "=f"(r0) : "f"(a0));
                asm("ex2.approx.f32 %0, %1;" : "=f"(r1) : "f"(a1));
                acc0 = fmaf(q.w, r0, acc0);
                acc1 = fmaf(q.w, r1, acc1);
            }
        } else {
            for (int j = 0; j < n; j++) {
                const float4 q = sP[wrp][j];
                float a0 = fmaf(q.x, gx0, fmaf(q.y, gy0, ga0 + q.z));
                float a1 = fmaf(q.x, gx1, fmaf(q.y, gy1, ga1 + q.z));
                float r0, r1;
                asm("ex2.approx.f32 %0, %1;" : "=f"(r0) : "f"(a0));
                asm("ex2.approx.f32 %0, %1;" : "=f"(r1) : "f"(a1));
                acc0 = fmaf(q.w, r0, acc0);
                acc1 = fmaf(q.w, r1, acc1);
            }
        }
        __syncwarp();
    }

    sRed[wrp][lane]      = acc0;
    sRed[wrp][lane + 32] = acc1;
    __syncthreads();
    if (tid < 64)
        g_X[g * 128 + branch * 64 + tid]
            = sRed[0][tid] + sRed[1][tid] + sRed[2][tid] + sRed[3][tid];
}

// -------------------------------------------------------------------------
// Kernel B: final MLP [B,144] -> relu 128 -> relu 128 -> 10.
// -------------------------------------------------------------------------
#define GPB 2
__global__ __launch_bounds__(128) void final_mlp_kernel(
    const float* __restrict__ gf,
    const float* __restrict__ Wr0, const float* __restrict__ br0,
    const float* __restrict__ Wr1, const float* __restrict__ br1,
    const float* __restrict__ Wro, const float* __restrict__ bro,
    float* __restrict__ out)
{
    __shared__ float sx[GPB][144];
    __shared__ float sh[GPB][128];
    const int g0  = blockIdx.x * GPB;
    const int tid = threadIdx.x;

    for (int idx = tid; idx < GPB * 144; idx += 128) {
        int gg = idx / 144, c = idx - gg * 144;
        sx[gg][c] = (c < 128) ? g_X[(g0 + gg) * 128 + c]
                              : gf[(g0 + gg) * 16 + (c - 128)];
    }
    __syncthreads();

    {
        float a0 = br0[tid], a1 = a0;
#pragma unroll 8
        for (int i = 0; i < 144; i++) {
            const float wv = Wr0[i * 128 + tid];
            a0 = fmaf(sx[0][i], wv, a0);
            a1 = fmaf(sx[1][i], wv, a1);
        }
        sh[0][tid] = fmaxf(a0, 0.f);
        sh[1][tid] = fmaxf(a1, 0.f);
    }
    __syncthreads();

    {
        float a0 = br1[tid], a1 = a0;
#pragma unroll 8
        for (int i = 0; i < 128; i++) {
            const float wv = Wr1[i * 128 + tid];
            a0 = fmaf(sh[0][i], wv, a0);
            a1 = fmaf(sh[1][i], wv, a1);
        }
        sx[0][tid] = fmaxf(a0, 0.f);
        sx[1][tid] = fmaxf(a1, 0.f);
    }
    __syncthreads();

    if (tid < GPB * NC) {
        const int gg = tid / NC, c = tid - gg * NC;
        float a = bro[c];
#pragma unroll 8
        for (int k = 0; k < 128; k++) a = fmaf(sx[gg][k], Wro[k * NC + c], a);
        out[(g0 + gg) * NC + c] = a;
    }
}

// -------------------------------------------------------------------------
extern "C" void kernel_launch(void* const* d_in, const int* in_sizes, int n_in,
                              void* d_out, int out_size)
{
    const float* diag0 = (const float*)d_in[0];
    const float* diag1 = (const float*)d_in[1];
    const float* gf    = (const float*)d_in[2];
    const float* theta = (const float*)d_in[3];
    const float* Ww0   = (const float*)d_in[4];
    const float* bw0   = (const float*)d_in[5];
    const float* Ww1   = (const float*)d_in[6];
    const float* bw1   = (const float*)d_in[7];
    const float* Wwo   = (const float*)d_in[8];
    const float* bwo   = (const float*)d_in[9];
    const float* Wr0   = (const float*)d_in[10];
    const float* br0   = (const float*)d_in[11];
    const float* Wr1   = (const float*)d_in[12];
    const float* br1   = (const float*)d_in[13];
    const float* Wro   = (const float*)d_in[14];
    const float* bro   = (const float*)d_in[15];
    const int*   batch0 = (const int*)d_in[16];
    const int*   batch1 = (const int*)d_in[17];

    dim3 sgrid((T_PTS + 255) / 256, 2);
    seg_bounds_kernel<<<sgrid, 256>>>(batch0, batch1);
    weight_mlp_mma<<<2 * B_GR, 128>>>(diag0, diag1,
                                      Ww0, bw0, Ww1, bw1, Wwo, bwo);
    gauss_pool_kernel<<<2 * B_GR, 128>>>(diag0, diag1, theta);
    final_mlp_kernel<<<B_GR / GPB, 128>>>(gf, Wr0, br0, Wr1, br1, Wro, bro,
                                          (float*)d_out);
}